// round 16
// baseline (speedup 1.0000x reference)
#include <cuda_runtime.h>
#include <cuda_fp16.h>
#include <cstdint>
#include <math.h>

// Shapes (fixed by the problem)
#define NB   2
#define TT   16
#define SS   256
#define DD   1024
#define MTOK (NB*TT*SS)        // 8192 tokens
#define QKVC (3*DD)            // 3072
#define HEADS 8
#define DH    64
#define SCALE 0.125f           // (1024/16)^-0.5

// ---------------------------------------------------------------------------
// Scratch (static device allocations — no cudaMalloc anywhere)
// ---------------------------------------------------------------------------
__device__ __align__(16) __half g_qkvh[MTOK * QKVC];   // [8192, 3072] fp16
__device__ __align__(16) __half g_xh[MTOK * DD];       // x in fp16
__device__ __align__(16) __half g_ah[MTOK * DD];       // attention out fp16
__device__ __align__(16) __half g_wqh[QKVC * DD];      // Wqkv^T [3072,1024] fp16
__device__ __align__(16) __half g_wph[DD * DD];        // Wproj^T [1024,1024] fp16

// ---------------------------------------------------------------------------
// PTX helpers
// ---------------------------------------------------------------------------
__device__ __forceinline__ uint32_t smem_to_u32(const void* p) {
    uint32_t a;
    asm("{ .reg .u64 t; cvta.to.shared.u64 t, %1; cvt.u32.u64 %0, t; }" : "=r"(a) : "l"(p));
    return a;
}

__device__ __forceinline__ void ldmatrix_x4(uint32_t& r0, uint32_t& r1,
                                            uint32_t& r2, uint32_t& r3, uint32_t addr) {
    asm volatile("ldmatrix.sync.aligned.m8n8.x4.shared.b16 {%0,%1,%2,%3}, [%4];"
                 : "=r"(r0), "=r"(r1), "=r"(r2), "=r"(r3) : "r"(addr));
}

__device__ __forceinline__ void ldmatrix_x4_trans(uint32_t& r0, uint32_t& r1,
                                                  uint32_t& r2, uint32_t& r3, uint32_t addr) {
    asm volatile("ldmatrix.sync.aligned.m8n8.x4.trans.shared.b16 {%0,%1,%2,%3}, [%4];"
                 : "=r"(r0), "=r"(r1), "=r"(r2), "=r"(r3) : "r"(addr));
}

__device__ __forceinline__ void mma16816(float* d, uint32_t a0, uint32_t a1,
                                         uint32_t a2, uint32_t a3,
                                         uint32_t b0, uint32_t b1) {
    asm volatile(
        "mma.sync.aligned.m16n8k16.row.col.f32.f16.f16.f32 "
        "{%0,%1,%2,%3}, {%4,%5,%6,%7}, {%8,%9}, {%0,%1,%2,%3};"
        : "+f"(d[0]), "+f"(d[1]), "+f"(d[2]), "+f"(d[3])
        : "r"(a0), "r"(a1), "r"(a2), "r"(a3), "r"(b0), "r"(b1));
}

__device__ __forceinline__ void cp_async16(uint32_t saddr, const void* gaddr) {
    asm volatile("cp.async.cg.shared.global [%0], [%1], 16;" :: "r"(saddr), "l"(gaddr));
}

__device__ __forceinline__ uint32_t f2h2(float lo, float hi) {
    __half2 h = __floats2half2_rn(lo, hi);
    return *(uint32_t*)&h;
}

// ---------------------------------------------------------------------------
// fp16 tensor-core GEMM: C[M,N] = A[M,K] @ B[N,K]^T (+ bias), fp32 accumulate.
// CTA tile 128x128, 4 warps (warp tile 64x64), K-chunk 64 (4 k16-steps),
// 3-stage cp.async pipeline (2 tiles/stage, 110.6 KB dynamic smem), 2 CTAs/SM.
// Rows padded to 144B (RSG=72): row step = 36 words == 4 mod 32 -> 8 rows of an
// 8x8 ldmatrix hit 8 distinct bank groups (conflict-free).
// ---------------------------------------------------------------------------
#define RSG 72             // padded row stride in fp16 elems (144 bytes)
#define GTILE_F (128*RSG)  // fp16 elems per tile region (9216)
#define NSTAGE 3
#define GEMM_SMEM_DYN (NSTAGE * 2 * GTILE_F * 2)   // 110592 bytes
#define KCHUNK 64

template <typename OutT>
__global__ __launch_bounds__(128, 2) void gemm_f16_mma(
    const __half* __restrict__ A, const __half* __restrict__ B,
    OutT* __restrict__ C, int M, int N, int K,
    const float* __restrict__ bias)
{
    extern __shared__ __half dsm[];  // [NSTAGE][2 tiles][GTILE_F]

    const int tid  = threadIdx.x;
    const int wid  = tid >> 5;
    const int lane = tid & 31;
    const int warp_m = wid & 1;      // 0..1 -> 64 rows each
    const int warp_n = wid >> 1;     // 0..1 -> 64 cols each
    const int m0 = blockIdx.y * 128;
    const int n0 = blockIdx.x * 128;

    const uint32_t sbase = smem_to_u32(dsm);
    #define TILE_U(s, t) (sbase + (uint32_t)(((s) * 2 + (t)) * GTILE_F * 2))

    float acc[4][8][4];
    #pragma unroll
    for (int i = 0; i < 4; i++)
        #pragma unroll
        for (int j = 0; j < 8; j++)
            #pragma unroll
            for (int q = 0; q < 4; q++) acc[i][j][q] = 0.f;

    const int niter = K / KCHUNK;

    // prefetch: per tile 128 rows x 64 halves = 1024 16B-chunks; 8 per thread
    auto prefetch = [&](int chunk, int stage) {
        const int k0 = chunk * KCHUNK;
        #pragma unroll
        for (int i = 0; i < 8; i++) {
            const int elem = tid + i * 128;
            const int r    = elem >> 3;      // 0..127
            const int c16  = elem & 7;       // 0..7 (16B chunk within 128B row)
            const uint32_t soff = (uint32_t)(r * RSG + c16 * 8) * 2;
            cp_async16(TILE_U(stage, 0) + soff, A + (size_t)(m0 + r) * K + k0 + c16 * 8);
            cp_async16(TILE_U(stage, 1) + soff, B + (size_t)(n0 + r) * K + k0 + c16 * 8);
        }
        asm volatile("cp.async.commit_group;");
    };

    prefetch(0, 0);
    prefetch(1, 1);

    const int am  = lane & 15;                        // A-pattern row
    const int akg = ((lane >> 4) << 3) * 2;           // A-pattern byte group
    const int bn  = (lane & 7) + ((lane >> 4) << 3);  // B-pattern row
    const int bkg = (((lane >> 3) & 1) << 3) * 2;     // B-pattern byte group

    int stage = 0, pstage = 2;
    for (int it = 0; it < niter; it++) {
        if (it + 1 < niter) {
            asm volatile("cp.async.wait_group 1;");
        } else {
            asm volatile("cp.async.wait_group 0;");
        }
        __syncthreads();

        if (it + 2 < niter) {
            prefetch(it + 2, pstage);
            pstage = (pstage == NSTAGE - 1) ? 0 : pstage + 1;
        }

        const uint32_t uA = TILE_U(stage, 0);
        const uint32_t uB = TILE_U(stage, 1);

        #pragma unroll
        for (int ks = 0; ks < 4; ks++) {
            uint32_t af[4][4];
            #pragma unroll
            for (int ms = 0; ms < 4; ms++) {
                const uint32_t arow = (uint32_t)(warp_m * 64 + ms * 16 + am) * (RSG * 2)
                                      + ks * 32 + akg;
                ldmatrix_x4(af[ms][0], af[ms][1], af[ms][2], af[ms][3], uA + arow);
            }
            uint32_t bf[4][4];
            #pragma unroll
            for (int nn = 0; nn < 4; nn++) {
                const uint32_t brow = (uint32_t)(warp_n * 64 + nn * 16 + bn) * (RSG * 2)
                                      + ks * 32 + bkg;
                ldmatrix_x4(bf[nn][0], bf[nn][1], bf[nn][2], bf[nn][3], uB + brow);
            }
            #pragma unroll
            for (int ms = 0; ms < 4; ms++)
                #pragma unroll
                for (int nn = 0; nn < 4; nn++) {
                    mma16816(acc[ms][nn * 2 + 0], af[ms][0], af[ms][1], af[ms][2], af[ms][3],
                             bf[nn][0], bf[nn][1]);
                    mma16816(acc[ms][nn * 2 + 1], af[ms][0], af[ms][1], af[ms][2], af[ms][3],
                             bf[nn][2], bf[nn][3]);
                }
        }
        stage = (stage == NSTAGE - 1) ? 0 : stage + 1;
    }
    #undef TILE_U

    // ---- epilogue ----
    #pragma unroll
    for (int ms = 0; ms < 4; ms++) {
        const int orow = m0 + warp_m * 64 + ms * 16 + (lane >> 2);
        const int ocol0 = n0 + warp_n * 64 + (lane & 3) * 2;
        #pragma unroll
        for (int nf = 0; nf < 8; nf++) {
            const int col = ocol0 + nf * 8;
            if constexpr (sizeof(OutT) == 2) {
                uint32_t u0 = f2h2(acc[ms][nf][0], acc[ms][nf][1]);
                uint32_t u1 = f2h2(acc[ms][nf][2], acc[ms][nf][3]);
                *(uint32_t*)((__half*)C + (size_t)orow * N + col) = u0;
                *(uint32_t*)((__half*)C + (size_t)(orow + 8) * N + col) = u1;
            } else {
                float b0 = 0.f, b1 = 0.f;
                if (bias) { b0 = bias[col]; b1 = bias[col + 1]; }
                float2 v0 = make_float2(acc[ms][nf][0] + b0, acc[ms][nf][1] + b1);
                float2 v1 = make_float2(acc[ms][nf][2] + b0, acc[ms][nf][3] + b1);
                *(float2*)((float*)C + (size_t)orow * N + col) = v0;
                *(float2*)((float*)C + (size_t)(orow + 8) * N + col) = v1;
            }
        }
    }
}

// ---------------------------------------------------------------------------
// fp32 -> fp16 convert / transpose
// ---------------------------------------------------------------------------
__global__ __launch_bounds__(256) void convert_h(
    const float4* __restrict__ in, uint2* __restrict__ outh, int n4)
{
    int i = blockIdx.x * blockDim.x + threadIdx.x;
    if (i >= n4) return;
    float4 v = in[i];
    union { __half b[4]; uint2 u; } H;
    H.b[0] = __float2half_rn(v.x);
    H.b[1] = __float2half_rn(v.y);
    H.b[2] = __float2half_rn(v.z);
    H.b[3] = __float2half_rn(v.w);
    outh[i] = H.u;
}

__global__ __launch_bounds__(256) void transpose_h(
    const float* __restrict__ W, __half* __restrict__ T, int K, int N)
{
    __shared__ float tile[32][33];
    const int n0 = blockIdx.x * 32;
    const int k0 = blockIdx.y * 32;
    for (int i = threadIdx.y; i < 32; i += 8)
        tile[i][threadIdx.x] = W[(size_t)(k0 + i) * N + n0 + threadIdx.x];
    __syncthreads();
    for (int i = threadIdx.y; i < 32; i += 8) {
        float v = tile[threadIdx.x][i];
        T[(size_t)(n0 + i) * K + k0 + threadIdx.x] = __float2half_rn(v);
    }
}

// ---------------------------------------------------------------------------
// Spatial attention via HMMA (flash-style): one block per (n,t,h).
// ---------------------------------------------------------------------------
#define RS2 72
#define SPAT_SMEM (3 * 256 * RS2 * 2)   // 110592 bytes

__global__ __launch_bounds__(256, 1) void spatial_attn_mma(
    const __half* __restrict__ qkvh, __half* __restrict__ ah)
{
    extern __shared__ __half sm2[];
    __half* Qs = sm2;
    __half* Ks = sm2 + 256 * RS2;
    __half* Vs = sm2 + 2 * 256 * RS2;

    const int b = blockIdx.x;
    const int h = b & 7;
    const int t = (b >> 3) & 15;
    const int n = b >> 7;
    const int tid = threadIdx.x;
    const int wid = tid >> 5;
    const int lane = tid & 31;
    const int frame_base = (n * TT + t) * SS;

    {
        const uint2* src = (const uint2*)qkvh;
        uint2* Q2 = (uint2*)Qs;
        uint2* K2 = (uint2*)Ks;
        uint2* V2 = (uint2*)Vs;
        for (int idx = tid; idx < 256 * 16; idx += 256) {
            const int s  = idx >> 4;
            const int d4 = idx & 15;
            const int base = (frame_base + s) * (QKVC / 4);
            const int dst = s * 18 + d4;
            Q2[dst] = src[base + h * 16 + d4];
            K2[dst] = src[base + 256 + h * 16 + d4];
            V2[dst] = src[base + 512 + h * 16 + d4];
        }
    }
    __syncthreads();

    const uint32_t uQ = smem_to_u32(Qs);
    const uint32_t uK = smem_to_u32(Ks);
    const uint32_t uV = smem_to_u32(Vs);

    uint32_t qf[2][4][4];
    {
        const int am = lane & 15;
        const int ac = (lane >> 4) << 4;
        #pragma unroll
        for (int ms = 0; ms < 2; ms++)
            #pragma unroll
            for (int kd = 0; kd < 4; kd++) {
                const uint32_t addr = uQ + (uint32_t)(wid * 32 + ms * 16 + am) * (RS2 * 2)
                                         + kd * 32 + ac;
                ldmatrix_x4(qf[ms][kd][0], qf[ms][kd][1], qf[ms][kd][2], qf[ms][kd][3], addr);
            }
    }

    float O[2][8][4];
    #pragma unroll
    for (int i = 0; i < 2; i++)
        #pragma unroll
        for (int j = 0; j < 8; j++)
            #pragma unroll
            for (int q = 0; q < 4; q++) O[i][j][q] = 0.f;
    float mrow[2][2] = { {-1e30f, -1e30f}, {-1e30f, -1e30f} };
    float lrow[2][2] = { {0.f, 0.f}, {0.f, 0.f} };

    const int bn = (lane & 7) + ((lane >> 4) << 3);
    const int bkh = ((lane >> 3) & 1) << 4;
    const int am = lane & 15;
    const int ac = (lane >> 4) << 4;

    for (int kc = 0; kc < 256; kc += 64) {
        float S[2][8][4];
        #pragma unroll
        for (int i = 0; i < 2; i++)
            #pragma unroll
            for (int j = 0; j < 8; j++)
                #pragma unroll
                for (int q = 0; q < 4; q++) S[i][j][q] = 0.f;

        #pragma unroll
        for (int t16 = 0; t16 < 4; t16++) {
            uint32_t kf[4][4];
            #pragma unroll
            for (int kd = 0; kd < 4; kd++) {
                const uint32_t addr = uK + (uint32_t)(kc + t16 * 16 + bn) * (RS2 * 2)
                                         + kd * 32 + bkh;
                ldmatrix_x4(kf[kd][0], kf[kd][1], kf[kd][2], kf[kd][3], addr);
            }
            #pragma unroll
            for (int ms = 0; ms < 2; ms++)
                #pragma unroll
                for (int kd = 0; kd < 4; kd++) {
                    mma16816(S[ms][t16 * 2 + 0], qf[ms][kd][0], qf[ms][kd][1],
                             qf[ms][kd][2], qf[ms][kd][3], kf[kd][0], kf[kd][1]);
                    mma16816(S[ms][t16 * 2 + 1], qf[ms][kd][0], qf[ms][kd][1],
                             qf[ms][kd][2], qf[ms][kd][3], kf[kd][2], kf[kd][3]);
                }
        }

        #pragma unroll
        for (int ms = 0; ms < 2; ms++) {
            float mx0 = -1e30f, mx1 = -1e30f;
            #pragma unroll
            for (int nf = 0; nf < 8; nf++) {
                mx0 = fmaxf(mx0, fmaxf(S[ms][nf][0], S[ms][nf][1]));
                mx1 = fmaxf(mx1, fmaxf(S[ms][nf][2], S[ms][nf][3]));
            }
            mx0 = fmaxf(mx0, __shfl_xor_sync(0xffffffffu, mx0, 1));
            mx0 = fmaxf(mx0, __shfl_xor_sync(0xffffffffu, mx0, 2));
            mx1 = fmaxf(mx1, __shfl_xor_sync(0xffffffffu, mx1, 1));
            mx1 = fmaxf(mx1, __shfl_xor_sync(0xffffffffu, mx1, 2));

            const float mn0 = fmaxf(mrow[ms][0], mx0);
            const float mn1 = fmaxf(mrow[ms][1], mx1);
            const float corr0 = __expf(SCALE * (mrow[ms][0] - mn0));
            const float corr1 = __expf(SCALE * (mrow[ms][1] - mn1));
            mrow[ms][0] = mn0;
            mrow[ms][1] = mn1;
            const float o0 = SCALE * mn0;
            const float o1 = SCALE * mn1;

            float s0 = 0.f, s1 = 0.f;
            #pragma unroll
            for (int nf = 0; nf < 8; nf++) {
                S[ms][nf][0] = __expf(fmaf(S[ms][nf][0], SCALE, -o0));
                S[ms][nf][1] = __expf(fmaf(S[ms][nf][1], SCALE, -o0));
                S[ms][nf][2] = __expf(fmaf(S[ms][nf][2], SCALE, -o1));
                S[ms][nf][3] = __expf(fmaf(S[ms][nf][3], SCALE, -o1));
                s0 += S[ms][nf][0] + S[ms][nf][1];
                s1 += S[ms][nf][2] + S[ms][nf][3];
            }
            s0 += __shfl_xor_sync(0xffffffffu, s0, 1);
            s0 += __shfl_xor_sync(0xffffffffu, s0, 2);
            s1 += __shfl_xor_sync(0xffffffffu, s1, 1);
            s1 += __shfl_xor_sync(0xffffffffu, s1, 2);
            lrow[ms][0] = lrow[ms][0] * corr0 + s0;
            lrow[ms][1] = lrow[ms][1] * corr1 + s1;

            #pragma unroll
            for (int nf = 0; nf < 8; nf++) {
                O[ms][nf][0] *= corr0; O[ms][nf][1] *= corr0;
                O[ms][nf][2] *= corr1; O[ms][nf][3] *= corr1;
            }
        }

        #pragma unroll
        for (int j = 0; j < 4; j++) {
            uint32_t vf[4][4];
            #pragma unroll
            for (int ng = 0; ng < 4; ng++) {
                const uint32_t addr = uV + (uint32_t)(kc + j * 16 + am) * (RS2 * 2)
                                         + ng * 32 + ac;
                ldmatrix_x4_trans(vf[ng][0], vf[ng][1], vf[ng][2], vf[ng][3], addr);
            }
            #pragma unroll
            for (int ms = 0; ms < 2; ms++) {
                const uint32_t a0 = f2h2(S[ms][2 * j][0],     S[ms][2 * j][1]);
                const uint32_t a1 = f2h2(S[ms][2 * j][2],     S[ms][2 * j][3]);
                const uint32_t a2 = f2h2(S[ms][2 * j + 1][0], S[ms][2 * j + 1][1]);
                const uint32_t a3 = f2h2(S[ms][2 * j + 1][2], S[ms][2 * j + 1][3]);
                #pragma unroll
                for (int ng = 0; ng < 4; ng++) {
                    mma16816(O[ms][ng * 2 + 0], a0, a1, a2, a3, vf[ng][0], vf[ng][1]);
                    mma16816(O[ms][ng * 2 + 1], a0, a1, a2, a3, vf[ng][2], vf[ng][3]);
                }
            }
        }
    }

    #pragma unroll
    for (int ms = 0; ms < 2; ms++) {
        const float inv0 = 1.f / lrow[ms][0];
        const float inv1 = 1.f / lrow[ms][1];
        const int row0 = frame_base + wid * 32 + ms * 16 + (lane >> 2);
        const int col0 = h * 64 + (lane & 3) * 2;
        #pragma unroll
        for (int nf = 0; nf < 8; nf++) {
            const int col = col0 + nf * 8;
            uint32_t u0 = f2h2(O[ms][nf][0] * inv0, O[ms][nf][1] * inv0);
            uint32_t u1 = f2h2(O[ms][nf][2] * inv1, O[ms][nf][3] * inv1);
            *(uint32_t*)(ah + (size_t)row0 * DD + col) = u0;
            *(uint32_t*)(ah + (size_t)(row0 + 8) * DD + col) = u1;
        }
    }
}

// ---------------------------------------------------------------------------
// Temporal attention: reads fp16 qkv (converts at fill), writes fp16.
// ---------------------------------------------------------------------------
#define TKS 516

__device__ __forceinline__ float4 h4_to_f4(uint2 raw) {
    __half2* hp = (__half2*)&raw;
    float2 f0 = __half22float2(hp[0]);
    float2 f1 = __half22float2(hp[1]);
    return make_float4(f0.x, f0.y, f1.x, f1.y);
}

__global__ __launch_bounds__(128, 1) void temporal_attn_kernel(
    const __half* __restrict__ qkvh, __half* __restrict__ ah)
{
    extern __shared__ float fsm[];
    float* Ks = fsm;
    float* Vs = fsm + 16 * TKS;

    const int b = blockIdx.x;
    const int s = b & 255;
    const int n = b >> 8;
    const int tid = threadIdx.x;

    for (int idx = tid; idx < 16 * 128; idx += 128) {
        int t  = idx >> 7;
        int c4 = idx & 127;
        int tok = (n * TT + t) * SS + s;
        const uint2* base = (const uint2*)(qkvh + (size_t)tok * QKVC);
        ((float4*)(Ks + t * TKS))[c4] = h4_to_f4(base[384 + c4]);
        ((float4*)(Vs + t * TKS))[c4] = h4_to_f4(base[640 + c4]);
    }
    __syncthreads();

    const int h  = tid >> 4;
    const int tq = tid & 15;
    const int tokq = (n * TT + tq) * SS + s;

    float4 q[16];
    const uint2* qb = (const uint2*)(qkvh + (size_t)tokq * QKVC);
    #pragma unroll
    for (int i = 0; i < 16; i++) q[i] = h4_to_f4(qb[128 + h * 16 + i]);

    float l[16];
    float m = -1e30f;
    #pragma unroll
    for (int kt = 0; kt < 16; kt++) {
        const float4* kp = (const float4*)(Ks + kt * TKS + h * 64);
        float dot = 0.f;
        #pragma unroll
        for (int i = 0; i < 16; i++) {
            float4 kv = kp[i];
            dot += q[i].x * kv.x + q[i].y * kv.y + q[i].z * kv.z + q[i].w * kv.w;
        }
        l[kt] = dot * SCALE;
        m = fmaxf(m, l[kt]);
    }
    float ssum = 0.f;
    #pragma unroll
    for (int kt = 0; kt < 16; kt++) { l[kt] = __expf(l[kt] - m); ssum += l[kt]; }
    float inv = 1.f / ssum;

    float4 acc[16];
    #pragma unroll
    for (int i = 0; i < 16; i++) acc[i] = make_float4(0.f, 0.f, 0.f, 0.f);
    #pragma unroll
    for (int kt = 0; kt < 16; kt++) {
        float p = l[kt] * inv;
        const float4* vp = (const float4*)(Vs + kt * TKS + h * 64);
        #pragma unroll
        for (int i = 0; i < 16; i++) {
            float4 vv = vp[i];
            acc[i].x += p * vv.x; acc[i].y += p * vv.y;
            acc[i].z += p * vv.z; acc[i].w += p * vv.w;
        }
    }

    uint2* out4 = (uint2*)ah;
    #pragma unroll
    for (int i = 0; i < 16; i++) {
        union { __half b[4]; uint2 u; } H;
        H.b[0] = __float2half_rn(acc[i].x);
        H.b[1] = __float2half_rn(acc[i].y);
        H.b[2] = __float2half_rn(acc[i].z);
        H.b[3] = __float2half_rn(acc[i].w);
        out4[tokq * (DD / 4) + 128 + h * 16 + i] = H.u;
    }
}

// ---------------------------------------------------------------------------
// Launch
// ---------------------------------------------------------------------------
extern "C" void kernel_launch(void* const* d_in, const int* in_sizes, int n_in,
                              void* d_out, int out_size)
{
    const float* x     = (const float*)d_in[0];
    const float* Wqkv  = (const float*)d_in[1];
    const float* Wproj = (const float*)d_in[2];
    const float* bproj = (const float*)d_in[3];
    float* out = (float*)d_out;

    __half *qkvh, *xh, *ah, *wqh, *wph;
    cudaGetSymbolAddress((void**)&qkvh, g_qkvh);
    cudaGetSymbolAddress((void**)&xh, g_xh);
    cudaGetSymbolAddress((void**)&ah, g_ah);
    cudaGetSymbolAddress((void**)&wqh, g_wqh);
    cudaGetSymbolAddress((void**)&wph, g_wph);

    const int temp_smem = 2 * 16 * TKS * (int)sizeof(float);   // 66048
    cudaFuncSetAttribute(spatial_attn_mma,
                         cudaFuncAttributeMaxDynamicSharedMemorySize, SPAT_SMEM);
    cudaFuncSetAttribute(temporal_attn_kernel,
                         cudaFuncAttributeMaxDynamicSharedMemorySize, temp_smem);
    cudaFuncSetAttribute(gemm_f16_mma<__half>,
                         cudaFuncAttributeMaxDynamicSharedMemorySize, GEMM_SMEM_DYN);
    cudaFuncSetAttribute(gemm_f16_mma<float>,
                         cudaFuncAttributeMaxDynamicSharedMemorySize, GEMM_SMEM_DYN);

    // 0) fp16 conversions / weight transposes
    const int n4x = MTOK * DD / 4;
    convert_h<<<n4x / 256, 256>>>((const float4*)x, (uint2*)xh, n4x);
    transpose_h<<<dim3(QKVC / 32, DD / 32), dim3(32, 8)>>>(Wqkv, wqh, DD, QKVC);
    transpose_h<<<dim3(DD / 32, DD / 32), dim3(32, 8)>>>(Wproj, wph, DD, DD);

    // 1) qkv = x @ Wqkv  (HMMA, fp16 output)
    gemm_f16_mma<__half><<<dim3(QKVC / 128, MTOK / 128), 128, GEMM_SMEM_DYN>>>(
        xh, wqh, qkvh, MTOK, QKVC, DD, nullptr);

    // 2) attention -> ah (fp16)
    spatial_attn_mma<<<NB * TT * HEADS, 256, SPAT_SMEM>>>(qkvh, ah);
    temporal_attn_kernel<<<NB * SS, 128, temp_smem>>>(qkvh, ah);

    // 3) out = att @ Wproj + bproj  (HMMA, fp32 output)
    gemm_f16_mma<float><<<dim3(DD / 128, MTOK / 128), 128, GEMM_SMEM_DYN>>>(
        ah, wph, out, MTOK, DD, DD, bproj);
}